// round 8
// baseline (speedup 1.0000x reference)
#include <cuda_runtime.h>
#include <cuda_bf16.h>
#include <math.h>
#include <stdint.h>

#define Cn   256
#define Hn   128
#define Wn   128
#define Bn   2
#define HWn  (Hn*Wn)        // 16384
#define NPIX (Bn*HWn)       // 32768
#define NCn  80
#define Kdcn 2304
#define WSZ  (Cn*Kdcn)      // 589824 words per layer
#define NCHUNK 72           // 2304/32
#define NELEM (Bn*Cn*HWn)   // 8388608
#define PKQ  (NELEM/4)      // 2097152

// ---- smem layout: per stage A 16KB ([128oc][128B row: 32 words hi|lo interleaved]),
//                   B 16KB ([128px][128B row]); XOR swizzle chunk^(row&7).
#define A_OFF 0
#define B_OFF 16384
#define STG   32768
#define META  (2*STG)             // 65536
#define SM_TOTAL (META + 9*128*32) // 102400

__device__ __forceinline__ uint32_t smem_to_u32(const void* p) {
    uint32_t a;
    asm("{ .reg .u64 t; cvta.to.shared.u64 t, %1; cvt.u32.u64 %0, t; }" : "=r"(a) : "l"(p));
    return a;
}
__device__ __forceinline__ void cpasync16(uint32_t dst, const void* src, uint32_t srcsz) {
    asm volatile("cp.async.cg.shared.global [%0], [%1], 16, %2;"
        :: "r"(dst), "l"(src), "r"(srcsz) : "memory");
}
__device__ __forceinline__ void cpcommit() {
    asm volatile("cp.async.commit_group;" ::: "memory");
}
__device__ __forceinline__ void cpwait0() {
    asm volatile("cp.async.wait_group 0;" ::: "memory");
}
__device__ __forceinline__ void ldsm4(uint32_t r[4], uint32_t addr) {
    asm volatile("ldmatrix.sync.aligned.m8n8.x4.shared.b16 {%0,%1,%2,%3}, [%4];"
        : "=r"(r[0]), "=r"(r[1]), "=r"(r[2]), "=r"(r[3]) : "r"(addr));
}
__device__ __forceinline__ void mma16816(float d[4], const uint32_t a[4],
                                         uint32_t b0, uint32_t b1) {
    asm volatile(
        "mma.sync.aligned.m16n8k16.row.col.f32.bf16.bf16.f32 "
        "{%0,%1,%2,%3}, {%4,%5,%6,%7}, {%8,%9}, {%0,%1,%2,%3};"
        : "+f"(d[0]), "+f"(d[1]), "+f"(d[2]), "+f"(d[3])
        : "r"(a[0]), "r"(a[1]), "r"(a[2]), "r"(a[3]), "r"(b0), "r"(b1));
}
__device__ __forceinline__ uint32_t prmt(uint32_t a, uint32_t b, uint32_t sel) {
    uint32_t d; asm("prmt.b32 %0,%1,%2,%3;" : "=r"(d) : "r"(a), "r"(b), "r"(sel));
    return d;
}
// packed word: low16 = bf16(v), high16 = bf16(v - bf16(v))
__device__ __forceinline__ uint32_t packpair(float v) {
    __nv_bfloat16 h = __float2bfloat16(v);
    float hf = __bfloat162float(h);
    __nv_bfloat16 l = __float2bfloat16(v - hf);
    uint16_t hb = *reinterpret_cast<uint16_t*>(&h);
    uint16_t lb = *reinterpret_cast<uint16_t*>(&l);
    return (uint32_t)hb | ((uint32_t)lb << 16);
}
// reconstruct fp32 from packed word (exact: hi + lo)
__device__ __forceinline__ float unpack(uint32_t pk) {
    return __int_as_float(pk << 16) + __int_as_float(pk & 0xFFFF0000u);
}

// ---------------- scratch (channel-last packed activations) ----------------
__device__ uint32_t g_pkX [NELEM];
__device__ uint32_t g_pkA [NELEM];
__device__ uint32_t g_pkB [NELEM];
__device__ uint32_t g_clspk[NELEM];
__device__ uint32_t g_ptspk[NELEM];
__device__ float g_bufA[NELEM];
__device__ float g_off [Bn*27*HWn];
__device__ float g_dcn [(size_t)Cn*NPIX];
__device__ __align__(16) uint32_t g_wpk[9*WSZ];

struct WPtrs { const float* w[9]; };

// ---------------- prep: pack x channel-last + all 9 weights (one launch) ----------------
__global__ void __launch_bounds__(256)
prep_kernel(const float* __restrict__ x, WPtrs wp,
            uint32_t* __restrict__ pkX, uint32_t* __restrict__ wpk)
{
    int gid = blockIdx.x * 256 + threadIdx.x;
    if (gid < PKQ) {
        int hw  = gid & (HWn - 1);
        int rem = gid >> 14;
        int cg  = rem & 63;
        int b   = rem >> 6;
        const float* src = x + ((size_t)(b*Cn + cg*4))*HWn + hw;
        uint4 o;
        o.x = packpair(__ldg(src));
        o.y = packpair(__ldg(src + HWn));
        o.z = packpair(__ldg(src + 2*HWn));
        o.w = packpair(__ldg(src + 3*HWn));
        *reinterpret_cast<uint4*>(pkX + ((size_t)(b*HWn + hw)*256 + cg*4)) = o;
    } else {
        int i = gid - PKQ;                 // < 9*WSZ
        int l = i / WSZ, r = i - l*WSZ;
        int oc = r / Kdcn, kp = r - oc*Kdcn;
        int tap = kp >> 8, ic = kp & 255;
        float v = wp.w[l][((size_t)oc*256 + ic)*9 + tap];
        wpk[i] = packpair(v);
    }
}

// =====================================================================
// Implicit-GEMM, interleaved hi/lo 2-pass MMA.
// D[128 oc][128 px] per CTA; 256 threads; 2 CTAs/SM; grid (256, 2).
// mode 0: conv3x3 pad1 from packed CL input; bias+relu; out fp32 NCHW and/or packed CL
// mode 1: dcn + mask; mode 2: dcn no mask; gather from packed CL; out fp32 [oc][NPIX]
// =====================================================================
__global__ void __launch_bounds__(256, 2)
gemm_kernel(int mode,
            const uint32_t* __restrict__ pkfeat,
            const uint32_t* __restrict__ wpk,
            const float* __restrict__ bias, const float* __restrict__ off,
            float* __restrict__ outf, uint32_t* __restrict__ outp)
{
    extern __shared__ __align__(128) char smem[];
    const uint32_t sbase = smem_to_u32(smem);
    const int tid  = threadIdx.x;
    const int wid  = tid >> 5, lane = tid & 31;
    const int nblk = blockIdx.x;
    const int b = nblk >> 7, y = nblk & 127;
    const int ocbase = blockIdx.y * 128;

    const int m0 = (wid & 3) * 32;     // 4 m-warps x 32 oc
    const int n0 = (wid >> 2) * 64;    // 2 n-warps x 64 px

    const int l7  = lane & 7;
    const int aR  = l7 + ((lane >> 3) & 1) * 8;
    const int bpx = l7 + (lane >> 4) * 8;

    // ---- dcn metadata: bilinear weights + corner indices per (tap, px) ----
    if (mode != 0) {
        for (int e = tid; e < 9*128; e += 256) {
            int tap = e >> 7, p = e & 127;
            int ky = tap / 3 - 1, kx = tap % 3 - 1;
            int hw = y * Wn + p;
            const float* offb = off + (size_t)b*27*HWn + hw;
            float offy = __ldg(offb + (size_t)(2*tap)*HWn);
            float offx = __ldg(offb + (size_t)(2*tap + 1)*HWn);
            float py = (float)(y + ky) + offy;
            float px = (float)(p + kx) + offx;
            float fy0 = floorf(py), fx0 = floorf(px);
            float ly = py - fy0, lx = px - fx0;
            bool vy0 = (fy0 >= 0.f)       && (fy0 <= 127.f);
            bool vy1 = (fy0 + 1.f >= 0.f) && (fy0 + 1.f <= 127.f);
            bool vx0 = (fx0 >= 0.f)       && (fx0 <= 127.f);
            bool vx1 = (fx0 + 1.f >= 0.f) && (fx0 + 1.f <= 127.f);
            float w00 = (1.f-ly)*(1.f-lx) * ((vy0 && vx0) ? 1.f : 0.f);
            float w01 = (1.f-ly)*lx       * ((vy0 && vx1) ? 1.f : 0.f);
            float w10 = ly*(1.f-lx)       * ((vy1 && vx0) ? 1.f : 0.f);
            float w11 = ly*lx             * ((vy1 && vx1) ? 1.f : 0.f);
            if (mode == 1) {
                float m = __ldg(offb + (size_t)(18 + tap)*HWn);
                w00 *= m; w01 *= m; w10 *= m; w11 *= m;
            }
            int iy0 = min(max((int)fy0,     0), Hn-1);
            int iy1 = min(max((int)fy0 + 1, 0), Hn-1);
            int ix0 = min(max((int)fx0,     0), Wn-1);
            int ix1 = min(max((int)fx0 + 1, 0), Wn-1);
            char* mb = smem + META + e*32;
            *reinterpret_cast<float4*>(mb) = make_float4(w00, w01, w10, w11);
            *reinterpret_cast<int4*>(mb + 16) =
                make_int4(iy0*Wn + ix0, iy0*Wn + ix1, iy1*Wn + ix0, iy1*Wn + ix1);
        }
        __syncthreads();
    }

    float acc[16][4];
    #pragma unroll
    for (int i = 0; i < 16; i++)
        #pragma unroll
        for (int j = 0; j < 4; j++) acc[i][j] = 0.f;

    // ---------------- loader ----------------
    auto load_chunk = [&](int stg, int cc) {
        const uint32_t su = sbase + stg * STG;
        // A: 128 oc x 32 words, cp.async with XOR swizzle
        {
            int row = tid >> 1, seg = tid & 1;
            const uint32_t* src = wpk + (size_t)(ocbase + row) * Kdcn + cc * 32;
            uint32_t drow = su + A_OFF + row * 128;
            int sw = row & 7;
            #pragma unroll
            for (int i = 0; i < 4; i++) {
                int ch = seg*4 + i;
                cpasync16(drow + ((ch ^ sw) << 4), src + ch*4, 16);
            }
        }
        const int tap = cc >> 3;
        const int ic0 = (cc & 7) * 32;

        if (mode == 0) {
            // B: one pixel row = 32 packed words = 128B contiguous in CL layout
            const int ky = tap / 3 - 1, kx = tap % 3 - 1;
            int p = tid >> 1, seg = tid & 1;
            int yy = y + ky, xx = p + kx;
            bool ok = (yy >= 0 && yy < Hn && xx >= 0 && xx < Wn);
            const uint32_t* src = pkfeat +
                ((size_t)(b*HWn + yy*Wn + xx)*256 + ic0);
            uint32_t srcsz = ok ? 16u : 0u;
            uint32_t drow = su + B_OFF + p * 128;
            int sw = p & 7;
            #pragma unroll
            for (int i = 0; i < 4; i++) {
                int ch = seg*4 + i;
                cpasync16(drow + ((ch ^ sw) << 4), src + ch*4, srcsz);
            }
            cpcommit();
        } else {
            cpcommit();
            // B via bilinear gather from packed CL
            int p = tid & 127, g = tid >> 7;     // g: 16-channel half
            const char* mb = smem + META + (tap*128 + p)*32;
            float4 wv = *reinterpret_cast<const float4*>(mb);
            int4  iv = *reinterpret_cast<const int4*>(mb + 16);
            const uint32_t* c0 = pkfeat + ((size_t)(b*HWn + iv.x)*256 + ic0 + g*16);
            const uint32_t* c1 = pkfeat + ((size_t)(b*HWn + iv.y)*256 + ic0 + g*16);
            const uint32_t* c2 = pkfeat + ((size_t)(b*HWn + iv.z)*256 + ic0 + g*16);
            const uint32_t* c3 = pkfeat + ((size_t)(b*HWn + iv.w)*256 + ic0 + g*16);
            uint32_t drow = su + B_OFF + p * 128;
            int sw = p & 7;
            #pragma unroll
            for (int q = 0; q < 4; q++) {
                uint4 u0 = *reinterpret_cast<const uint4*>(c0 + q*4);
                uint4 u1 = *reinterpret_cast<const uint4*>(c1 + q*4);
                uint4 u2 = *reinterpret_cast<const uint4*>(c2 + q*4);
                uint4 u3 = *reinterpret_cast<const uint4*>(c3 + q*4);
                uint4 o;
                o.x = packpair(wv.x*unpack(u0.x) + wv.y*unpack(u1.x) + wv.z*unpack(u2.x) + wv.w*unpack(u3.x));
                o.y = packpair(wv.x*unpack(u0.y) + wv.y*unpack(u1.y) + wv.z*unpack(u2.y) + wv.w*unpack(u3.y));
                o.z = packpair(wv.x*unpack(u0.z) + wv.y*unpack(u1.z) + wv.z*unpack(u2.z) + wv.w*unpack(u3.z));
                o.w = packpair(wv.x*unpack(u0.w) + wv.y*unpack(u1.w) + wv.z*unpack(u2.w) + wv.w*unpack(u3.w));
                int ch = g*4 + q;
                *reinterpret_cast<uint4*>(smem + (drow - sbase) + ((ch ^ sw) << 4)) = o;
            }
        }
    };

    // ---------------- compute: 2-pass interleaved hi/lo ----------------
    auto compute = [&](int stg) {
        const uint32_t Ab = sbase + stg*STG + A_OFF;
        const uint32_t Bb = sbase + stg*STG + B_OFF;
        #pragma unroll
        for (int s2 = 0; s2 < 4; s2++) {
            uint32_t cxA = (uint32_t)(((s2*2 + (lane >> 4)) ^ l7) << 4);
            uint32_t cxB = (uint32_t)(((s2*2 + ((lane >> 3) & 1)) ^ l7) << 4);
            uint32_t a0[4], a1[4], s0[4], s1[4];
            ldsm4(a0, Ab + (uint32_t)((m0 + aR)*128)      + cxA);
            ldsm4(a1, Ab + (uint32_t)((m0 + 16 + aR)*128) + cxA);
            #pragma unroll
            for (int j = 0; j < 4; j++) {
                s0[j] = prmt(a0[j], a0[j], 0x1032);
                s1[j] = prmt(a1[j], a1[j], 0x1032);
            }
            #pragma unroll
            for (int nb = 0; nb < 4; nb++) {
                uint32_t bb[4];
                ldsm4(bb, Bb + (uint32_t)((n0 + nb*16 + bpx)*128) + cxB);
                mma16816(acc[nb*2 + 0],     a0, bb[0], bb[1]);
                mma16816(acc[nb*2 + 1],     a0, bb[2], bb[3]);
                mma16816(acc[8 + nb*2 + 0], a1, bb[0], bb[1]);
                mma16816(acc[8 + nb*2 + 1], a1, bb[2], bb[3]);
                mma16816(acc[nb*2 + 0],     s0, bb[0], bb[1]);
                mma16816(acc[nb*2 + 1],     s0, bb[2], bb[3]);
                mma16816(acc[8 + nb*2 + 0], s1, bb[0], bb[1]);
                mma16816(acc[8 + nb*2 + 1], s1, bb[2], bb[3]);
            }
        }
    };

    // ---------------- pipelined main loop ----------------
    load_chunk(0, 0);
    cpwait0();
    __syncthreads();
    for (int c = 0; c < NCHUNK; c++) {
        int cur = c & 1;
        if (c + 1 < NCHUNK) load_chunk(cur ^ 1, c + 1);
        compute(cur);
        cpwait0();
        __syncthreads();
    }

    // ---------------- epilogue ----------------
    const int r  = lane >> 2;
    const int c2 = (lane & 3) * 2;
    #pragma unroll
    for (int mt = 0; mt < 2; mt++) {
        #pragma unroll
        for (int rr = 0; rr < 2; rr++) {
            int oc = ocbase + m0 + mt*16 + r + rr*8;
            float bv = (mode == 0 && bias) ? __ldg(&bias[oc]) : 0.f;
            #pragma unroll
            for (int nt = 0; nt < 8; nt++) {
                float* d = acc[mt*8 + nt];
                int x = n0 + nt*8 + c2;
                float v0 = fmaxf(d[rr*2]   + bv, 0.f);
                float v1 = fmaxf(d[rr*2+1] + bv, 0.f);
                if (mode == 0) {
                    if (outf) {
                        float2 fv = { v0, v1 };
                        *reinterpret_cast<float2*>(outf +
                            ((size_t)(b*Cn + oc))*HWn + y*Wn + x) = fv;
                    }
                    if (outp) {
                        size_t pb = ((size_t)(b*HWn + y*Wn + x)) << 8;
                        outp[pb + oc]       = packpair(v0);
                        outp[pb + 256 + oc] = packpair(v1);
                    }
                } else {
                    float2 fv = { v0, v1 };
                    *reinterpret_cast<float2*>(outf +
                        (size_t)oc*NPIX + (size_t)b*HWn + y*Wn + x) = fv;
                }
            }
        }
    }
}

// ---------------- small kernels ----------------
__global__ void __launch_bounds__(256)
conv1x1_27_kernel(const float* __restrict__ in, const float* __restrict__ wgt,
                  const float* __restrict__ bias, float* __restrict__ out)
{
    __shared__ float ws[Cn*27];
    for (int idx = threadIdx.x; idx < Cn*27; idx += 256) {
        int o = idx >> 8, ic = idx & 255;
        ws[ic*27 + o] = wgt[(size_t)o*Cn + ic];
    }
    __syncthreads();
    int p  = blockIdx.x * 256 + threadIdx.x;
    int b  = p >> 14;
    int hw = p & (HWn - 1);
    float acc[27];
    #pragma unroll
    for (int o = 0; o < 27; o++) acc[o] = 0.f;
    const float* ip = in + (size_t)b*Cn*HWn + hw;
    for (int ic = 0; ic < Cn; ic++) {
        float v = __ldg(ip + (size_t)ic*HWn);
        #pragma unroll
        for (int o = 0; o < 27; o++) acc[o] += v * ws[ic*27 + o];
    }
    #pragma unroll
    for (int o = 0; o < 27; o++)
        out[((size_t)(b*27) + o)*HWn + hw] = acc[o] + bias[o];
}

__global__ void __launch_bounds__(256)
conv1x1_cls_kernel(const float* __restrict__ in, const float* __restrict__ wgt,
                   const float* __restrict__ bias, float* __restrict__ out)
{
    __shared__ float ws[Cn*16];
    int g = blockIdx.y;
    for (int idx = threadIdx.x; idx < Cn*16; idx += 256) {
        int j = idx >> 8, ic = idx & 255;
        ws[ic*16 + j] = wgt[(size_t)(g*16 + j)*Cn + ic];
    }
    __syncthreads();
    int p  = blockIdx.x * 256 + threadIdx.x;
    int b  = p >> 14;
    int hw = p & (HWn - 1);
    float acc[16];
    #pragma unroll
    for (int j = 0; j < 16; j++) acc[j] = 0.f;
    for (int ic = 0; ic < Cn; ic++) {
        float v = __ldg(&in[(size_t)ic*NPIX + p]);
        #pragma unroll
        for (int j = 0; j < 16; j++) acc[j] += v * ws[ic*16 + j];
    }
    #pragma unroll
    for (int j = 0; j < 16; j++) {
        int oc = g*16 + j;
        out[((size_t)(b*NCn) + oc)*HWn + hw] = acc[j] + bias[oc];
    }
}

__global__ void __launch_bounds__(256)
ref_fused_kernel(const float* __restrict__ in, const float* __restrict__ wgt,
                 const float* __restrict__ bias, const float* __restrict__ off,
                 float* __restrict__ dout)
{
    __shared__ float ws[Cn*18];
    for (int idx = threadIdx.x; idx < Cn*18; idx += 256) {
        int o = idx >> 8, ic = idx & 255;
        ws[ic*18 + o] = wgt[(size_t)o*Cn + ic];
    }
    __syncthreads();
    int p  = blockIdx.x * 256 + threadIdx.x;
    int b  = p >> 14;
    int hw = p & (HWn - 1);
    float acc[18];
    #pragma unroll
    for (int o = 0; o < 18; o++) acc[o] = 0.f;
    for (int ic = 0; ic < Cn; ic++) {
        float v = __ldg(&in[(size_t)ic*NPIX + p]);
        #pragma unroll
        for (int o = 0; o < 18; o++) acc[o] += v * ws[ic*18 + o];
    }
    float refine[18];
    #pragma unroll
    for (int o = 0; o < 18; o++)
        refine[o] = acc[o] + bias[o] + off[((size_t)(b*27) + o)*HWn + hw];
    float m0 = 0.f, m1 = 0.f;
    #pragma unroll
    for (int q = 0; q < 9; q++) { m0 += refine[2*q]; m1 += refine[2*q + 1]; }
    m0 *= (1.f/9.f); m1 *= (1.f/9.f);
    float wh0 = 0.f, wh1 = 0.f;
    #pragma unroll
    for (int q = 0; q < 9; q++) {
        wh0 = fmaxf(wh0, fabsf(refine[2*q]     + m0));
        wh1 = fmaxf(wh1, fabsf(refine[2*q + 1] + m1));
    }
    const size_t OUT_WH  = (size_t)Bn*NCn*HWn;
    const size_t OUT_REG = OUT_WH + (size_t)Bn*2*HWn;
    dout[OUT_WH  + ((size_t)(b*2) + 0)*HWn + hw] = wh0;
    dout[OUT_WH  + ((size_t)(b*2) + 1)*HWn + hw] = wh1;
    dout[OUT_REG + ((size_t)(b*2) + 0)*HWn + hw] = m0;
    dout[OUT_REG + ((size_t)(b*2) + 1)*HWn + hw] = m1;
}

// =====================================================================
extern "C" void kernel_launch(void* const* d_in, const int* in_sizes, int n_in,
                              void* d_out, int out_size)
{
    const float* x = (const float*)d_in[0];
    WPtrs wp;
    wp.w[0] = (const float*)d_in[1];   // cls_w0
    wp.w[1] = (const float*)d_in[5];   // cls_w1
    wp.w[2] = (const float*)d_in[9];   // cls_w2
    wp.w[3] = (const float*)d_in[3];   // reg_w0
    wp.w[4] = (const float*)d_in[7];   // reg_w1
    wp.w[5] = (const float*)d_in[11];  // reg_w2
    wp.w[6] = (const float*)d_in[13];  // init_conv_w
    wp.w[7] = (const float*)d_in[17];  // dcn_cls_w
    wp.w[8] = (const float*)d_in[20];  // dcn_ref_w
    const float* cls_b0      = (const float*)d_in[2];
    const float* cls_b1      = (const float*)d_in[6];
    const float* cls_b2      = (const float*)d_in[10];
    const float* reg_b0      = (const float*)d_in[4];
    const float* reg_b1      = (const float*)d_in[8];
    const float* reg_b2      = (const float*)d_in[12];
    const float* init_conv_b = (const float*)d_in[14];
    const float* init_out_w  = (const float*)d_in[15];
    const float* init_out_b  = (const float*)d_in[16];
    const float* cls_out_w   = (const float*)d_in[18];
    const float* cls_out_b   = (const float*)d_in[19];
    const float* ref_out_w   = (const float*)d_in[21];
    const float* ref_out_b   = (const float*)d_in[22];
    float* out = (float*)d_out;

    uint32_t *pkX, *pkA, *pkB, *clspk, *ptspk, *wpk;
    float *bufA, *off, *dcn;
    cudaGetSymbolAddress((void**)&pkX,   g_pkX);
    cudaGetSymbolAddress((void**)&pkA,   g_pkA);
    cudaGetSymbolAddress((void**)&pkB,   g_pkB);
    cudaGetSymbolAddress((void**)&clspk, g_clspk);
    cudaGetSymbolAddress((void**)&ptspk, g_ptspk);
    cudaGetSymbolAddress((void**)&wpk,   g_wpk);
    cudaGetSymbolAddress((void**)&bufA,  g_bufA);
    cudaGetSymbolAddress((void**)&off,   g_off);
    cudaGetSymbolAddress((void**)&dcn,   g_dcn);

    cudaFuncSetAttribute(gemm_kernel, cudaFuncAttributeMaxDynamicSharedMemorySize, SM_TOTAL);

    #define GEMM(md, in_, l, bias_, off_, of_, op_) \
        gemm_kernel<<<dim3(256, 2), 256, SM_TOTAL>>>(md, in_, wpk + (size_t)(l)*WSZ, \
                                                     bias_, off_, of_, op_)

    prep_kernel<<<(PKQ + 9*WSZ)/256, 256>>>(x, wp, pkX, wpk);

    // cls tower (channel-last packed chain)
    GEMM(0, pkX, 0, cls_b0, nullptr, nullptr, pkA);
    GEMM(0, pkA, 1, cls_b1, nullptr, nullptr, pkB);
    GEMM(0, pkB, 2, cls_b2, nullptr, nullptr, clspk);
    // reg tower
    GEMM(0, pkX, 3, reg_b0, nullptr, nullptr, pkA);
    GEMM(0, pkA, 4, reg_b1, nullptr, nullptr, pkB);
    GEMM(0, pkB, 5, reg_b2, nullptr, nullptr, ptspk);
    // init branch (fp32 NCHW for the 1x1 head)
    GEMM(0, ptspk, 6, init_conv_b, nullptr, bufA, nullptr);
    conv1x1_27_kernel<<<128, 256>>>(bufA, init_out_w, init_out_b, off);

    // cls dcn (mask) -> cls head
    GEMM(1, clspk, 7, nullptr, off, dcn, nullptr);
    conv1x1_cls_kernel<<<dim3(128, 5), 256>>>(dcn, cls_out_w, cls_out_b, out);

    // ref dcn (no mask) -> fused refine/wh/reg
    GEMM(2, ptspk, 8, nullptr, off, dcn, nullptr);
    ref_fused_kernel<<<128, 256>>>(dcn, ref_out_w, ref_out_b, off, out);
}